// round 13
// baseline (speedup 1.0000x reference)
#include <cuda_runtime.h>
#include <math.h>
#include <stdint.h>

// Problem constants
#define B_   4
#define T_   2048
#define D_   1024
#define H_   16
#define DH_  64
#define NTOK (B_ * T_)     // 8192
#define E3   (3 * D_)      // 3072

// softmax scale folded with log2(e): logits come out in base-2 units
#define QSCALE 0.18033688011112042f   // 0.125 * log2(e)

// Scratch (device globals: allocation-free rule)
__device__ __align__(16) float g_qkv[NTOK * E3];   // [8192, 3072] (pre-rounded, Q pre-scaled)
__device__ __align__(16) float g_att[NTOK * D_];   // [8192, 1024] (pre-rounded)
__device__ __align__(16) float g_xr [NTOK * D_];   // tf32-rounded x
__device__ __align__(16) float g_war[E3 * D_];     // tf32-rounded w_attn
__device__ __align__(16) float g_wpr[D_ * D_];     // tf32-rounded w_proj

// ---------------------------------------------------------------------------
// Helpers
// ---------------------------------------------------------------------------
__device__ __forceinline__ float tf32r(float x) {
    uint32_t u;
    asm("cvt.rna.tf32.f32 %0, %1;" : "=r"(u) : "f"(x));
    return __uint_as_float(u);
}

__device__ __forceinline__ float ex2f(float x) {
    float r;
    asm("ex2.approx.ftz.f32 %0, %1;" : "=f"(r) : "f"(x));
    return r;
}

__device__ __forceinline__ void mma_tf32(float* c, const float* a, float b0, float b1) {
    asm volatile(
        "mma.sync.aligned.m16n8k8.row.col.f32.tf32.tf32.f32 "
        "{%0,%1,%2,%3}, {%4,%5,%6,%7}, {%8,%9}, {%0,%1,%2,%3};\n"
        : "+f"(c[0]), "+f"(c[1]), "+f"(c[2]), "+f"(c[3])
        : "r"(__float_as_uint(a[0])), "r"(__float_as_uint(a[1])),
          "r"(__float_as_uint(a[2])), "r"(__float_as_uint(a[3])),
          "r"(__float_as_uint(b0)), "r"(__float_as_uint(b1)));
}

__device__ __forceinline__ void mma_tf32u(float* c, const uint32_t* a,
                                          uint32_t b0, uint32_t b1) {
    asm volatile(
        "mma.sync.aligned.m16n8k8.row.col.f32.tf32.tf32.f32 "
        "{%0,%1,%2,%3}, {%4,%5,%6,%7}, {%8,%9}, {%0,%1,%2,%3};\n"
        : "+f"(c[0]), "+f"(c[1]), "+f"(c[2]), "+f"(c[3])
        : "r"(a[0]), "r"(a[1]), "r"(a[2]), "r"(a[3]), "r"(b0), "r"(b1));
}

// ldmatrix.x4: four 8x8 b16 matrices == four 8x4 tf32 tiles; thread n gets
// tf32 element (n>>2, n&3) of each tile -> exact mma fragment mapping.
__device__ __forceinline__ void ldsm_x4(uint32_t* r, const float* p) {
    uint32_t a = (uint32_t)__cvta_generic_to_shared(p);
    asm volatile("ldmatrix.sync.aligned.m8n8.x4.shared.b16 {%0,%1,%2,%3}, [%4];"
                 : "=r"(r[0]), "=r"(r[1]), "=r"(r[2]), "=r"(r[3]) : "r"(a));
}

__device__ __forceinline__ void cp_async16(void* smem_dst, const void* gsrc) {
    uint32_t s = (uint32_t)__cvta_generic_to_shared(smem_dst);
    asm volatile("cp.async.cg.shared.global [%0], [%1], 16;\n" :: "r"(s), "l"(gsrc) : "memory");
}
__device__ __forceinline__ void cp_commit() {
    asm volatile("cp.async.commit_group;\n" ::: "memory");
}
template<int N>
__device__ __forceinline__ void cp_wait() {
    asm volatile("cp.async.wait_group %0;\n" :: "n"(N) : "memory");
}

// ---------------------------------------------------------------------------
// Pre-round to tf32 (rna), elementwise
// ---------------------------------------------------------------------------
__global__ void round_tf32_kernel(const float4* __restrict__ in,
                                  float4* __restrict__ out, int n4)
{
    int i = blockIdx.x * blockDim.x + threadIdx.x;
    if (i < n4) {
        float4 v = in[i];
        v.x = tf32r(v.x); v.y = tf32r(v.y); v.z = tf32r(v.z); v.w = tf32r(v.w);
        out[i] = v;
    }
}

// ---------------------------------------------------------------------------
// TF32 NT GEMM, inputs pre-rounded. BM=BN=128, BK=32, 3-stage cp.async
// pipeline with ONE barrier per k-iter (issue hoisted above compute).
// 256 threads (8 warps), warp tile 64x32, LDSM fragment loads.
// ---------------------------------------------------------------------------
#define BM 128
#define BN 128
#define BK 32
#define TSTR 36                                   // 32 + 4 pad words
#define GEMM_STAGE_WORDS (BM * TSTR)              // 4608 words per tile
#define GEMM_SMEM_BYTES (3 * 2 * GEMM_STAGE_WORDS * 4)   // 110592

__global__ void __launch_bounds__(256, 2)
gemm_nt_tf32(const float* __restrict__ A, const float* __restrict__ Bm,
             float* __restrict__ C, int M, int N, int K, int qkv_mode)
{
    extern __shared__ float smg[];
    const int SW = GEMM_STAGE_WORDS;

    const int tid  = threadIdx.x;
    const int lane = tid & 31;
    const int warp = tid >> 5;
    const int wm   = (warp >> 2) * 64;
    const int wn   = (warp & 3) * 32;
    const int m0   = blockIdx.y * BM;
    const int n0   = blockIdx.x * BN;

    // LDSM per-thread source pattern
    const int l8      = lane & 7;
    const int aRowOff = ((lane >> 3) & 1) * 8;
    const int aColOff = (lane >> 4) * 4;
    const int bRowOff = ((lane >> 4) & 1) * 8;
    const int bColOff = ((lane >> 3) & 1) * 4;

    float acc[4][4][4] = {};

    const int nIter = K / BK;

    auto issue = [&](int it, int s) {
        float* As = smg + s * 2 * SW;
        float* Bs = As + SW;
        int k0 = it * BK;
        #pragma unroll
        for (int i = 0; i < 4; ++i) {
            int c   = tid + i * 256;
            int row = c >> 3;
            int lk  = (c & 7) << 2;
            cp_async16(&As[row * TSTR + lk], &A[(size_t)(m0 + row) * K + k0 + lk]);
            cp_async16(&Bs[row * TSTR + lk], &Bm[(size_t)(n0 + row) * K + k0 + lk]);
        }
        cp_commit();
    };

    issue(0, 0);
    issue(1, 1);

    for (int it = 0; it < nIter; ++it) {
        const int s = it % 3;
        cp_wait<1>();          // group `it` complete (group it+1 may remain)
        __syncthreads();       // all warps done with stage (it-1)%3 == (it+2)%3

        // Prefetch it+2 into the stage consumed at it-1 (safe after the sync)
        if (it + 2 < nIter) issue(it + 2, (it + 2) % 3);
        else cp_commit();      // keep group numbering uniform

        const float* As = smg + s * 2 * SW;
        const float* Bs = As + SW;

        #pragma unroll
        for (int ks = 0; ks < BK; ks += 8) {
            uint32_t af[4][4], bf[2][4];
            #pragma unroll
            for (int mi = 0; mi < 4; ++mi)
                ldsm_x4(af[mi], &As[(wm + mi * 16 + aRowOff + l8) * TSTR + ks + aColOff]);
            #pragma unroll
            for (int p = 0; p < 2; ++p)
                ldsm_x4(bf[p], &Bs[(wn + p * 16 + bRowOff + l8) * TSTR + ks + bColOff]);
            #pragma unroll
            for (int mi = 0; mi < 4; ++mi)
                #pragma unroll
                for (int nj = 0; nj < 4; ++nj)
                    mma_tf32u(acc[mi][nj], af[mi],
                              bf[nj >> 1][(nj & 1) * 2], bf[nj >> 1][(nj & 1) * 2 + 1]);
        }
    }

    const bool doRound = (qkv_mode != 0);
    const float esc = (doRound && n0 < D_) ? QSCALE : 1.0f;

    #pragma unroll
    for (int mi = 0; mi < 4; ++mi) {
        int row = m0 + wm + mi * 16 + (lane >> 2);
        #pragma unroll
        for (int nj = 0; nj < 4; ++nj) {
            int col = n0 + wn + nj * 8 + ((lane & 3) << 1);
            float2 v0 = make_float2(acc[mi][nj][0] * esc, acc[mi][nj][1] * esc);
            float2 v1 = make_float2(acc[mi][nj][2] * esc, acc[mi][nj][3] * esc);
            if (doRound) {
                v0.x = tf32r(v0.x); v0.y = tf32r(v0.y);
                v1.x = tf32r(v1.x); v1.y = tf32r(v1.y);
            }
            *(float2*)&C[(size_t)row * N + col]       = v0;
            *(float2*)&C[(size_t)(row + 8) * N + col] = v1;
        }
    }
}

// ---------------------------------------------------------------------------
// Flash attention on tensor cores. BLOCK_M=128 q rows (8 warps x 16 rows),
// key tiles of 64, DH=64, 256 threads. K/V double-buffered via cp.async;
// Q/K fragments via LDSM; P stays in registers (quad-shuffle permutation).
// ---------------------------------------------------------------------------
#define ATM 128
#define AT_STR 68
// Qb[128][68] + 2 stages x (Kb[64][68] + Vs[64][68])
#define ATTN_SMEM_BYTES (384 * AT_STR * 4)   // 104448

__global__ void __launch_bounds__(256, 2)
attn_mma_kernel(const float* __restrict__ qkv, float* __restrict__ out)
{
    extern __shared__ float sm[];
    float* Qb = sm;                   // [row][d]
    float* KV = Qb + ATM * AT_STR;    // stage s: K at s*2*64*68, V at +64*68

    const int tid  = threadIdx.x;
    const int lane = tid & 31;
    const int warp = tid >> 5;        // 0..7
    const int g    = lane >> 2;       // 0..7
    const int t    = lane & 3;        // 0..3
    const int m0   = warp * 16;
    const int qt   = gridDim.x - 1 - blockIdx.x;   // big tiles first
    const int h    = blockIdx.y;
    const int b    = blockIdx.z;

    // LDSM per-thread source pattern
    const int l8      = lane & 7;
    const int aRowOff = ((lane >> 3) & 1) * 8;
    const int aColOff = (lane >> 4) * 4;
    const int bRowOff = ((lane >> 4) & 1) * 8;
    const int bColOff = ((lane >> 3) & 1) * 4;

    // Q tile load (pre-scaled + pre-rounded by GEMM epilogue)
    const float* qbase = qkv + (size_t)(b * T_ + qt * ATM) * E3 + h * DH_;
    #pragma unroll
    for (int i = 0; i < 8; ++i) {
        int c = tid + i * 256;
        int row = c >> 4, c4 = (c & 15) << 2;
        cp_async16(&Qb[row * AT_STR + c4], qbase + (size_t)row * E3 + c4);
    }
    cp_commit();

    const int nTiles = 2 * qt + 2;

    auto issueKV = [&](int n, int s) {
        const float* kbase = qkv + (size_t)(b * T_ + n * 64) * E3 + D_ + h * DH_;
        float* Kb = KV + s * 2 * 64 * AT_STR;
        float* Vb = Kb + 64 * AT_STR;
        #pragma unroll
        for (int i = 0; i < 4; ++i) {
            int c = tid + i * 256;
            int row = c >> 4, c4 = (c & 15) << 2;
            const float* kp = kbase + (size_t)row * E3 + c4;
            cp_async16(&Kb[row * AT_STR + c4], kp);
            cp_async16(&Vb[row * AT_STR + c4], kp + D_);
        }
        cp_commit();
    };

    issueKV(0, 0);
    issueKV(1, 1);

    float pacc[8][4] = {};
    float m0r = -3.0e38f, m1r = -3.0e38f;
    float l0 = 0.0f, l1 = 0.0f;

    const int src0 = (lane & 28) | (t >> 1);   // quad-shuffle source lanes
    const bool odd = (t & 1);

    for (int n = 0; n < nTiles; ++n) {
        const int s = n & 1;
        if (n + 1 < nTiles) cp_wait<1>();
        else                cp_wait<0>();
        __syncthreads();

        const float* Kb = KV + s * 2 * 64 * AT_STR;
        const float* Vb = Kb + 64 * AT_STR;

        // S = Q @ K^T   (rows m0..m0+15), LDSM fragment loads
        float sacc[8][4] = {};
        #pragma unroll
        for (int ks = 0; ks < 64; ks += 8) {
            uint32_t aq[4], kb[4][4];
            ldsm_x4(aq, &Qb[(m0 + aRowOff + l8) * AT_STR + ks + aColOff]);
            #pragma unroll
            for (int p = 0; p < 4; ++p)
                ldsm_x4(kb[p], &Kb[(p * 16 + bRowOff + l8) * AT_STR + ks + bColOff]);
            #pragma unroll
            for (int j = 0; j < 8; ++j)
                mma_tf32u(sacc[j], aq,
                          kb[j >> 1][(j & 1) * 2], kb[j >> 1][(j & 1) * 2 + 1]);
        }

        // Causal mask on tiles crossing the diagonal (global indices)
        if (n >= 2 * qt) {
            int rg0 = qt * ATM + m0 + g;
            int rg1 = rg0 + 8;
            #pragma unroll
            for (int j = 0; j < 8; ++j) {
                int c0 = n * 64 + j * 8 + 2 * t, c1 = c0 + 1;
                if (c0 > rg0) sacc[j][0] = -3.0e38f;
                if (c1 > rg0) sacc[j][1] = -3.0e38f;
                if (c0 > rg1) sacc[j][2] = -3.0e38f;
                if (c1 > rg1) sacc[j][3] = -3.0e38f;
            }
        }

        // Online softmax in base-2 units (register frags, quad shuffles)
        float mx0 = -3.0e38f, mx1 = -3.0e38f;
        #pragma unroll
        for (int j = 0; j < 8; ++j) {
            mx0 = fmaxf(mx0, fmaxf(sacc[j][0], sacc[j][1]));
            mx1 = fmaxf(mx1, fmaxf(sacc[j][2], sacc[j][3]));
        }
        mx0 = fmaxf(mx0, __shfl_xor_sync(0xffffffffu, mx0, 1));
        mx0 = fmaxf(mx0, __shfl_xor_sync(0xffffffffu, mx0, 2));
        mx1 = fmaxf(mx1, __shfl_xor_sync(0xffffffffu, mx1, 1));
        mx1 = fmaxf(mx1, __shfl_xor_sync(0xffffffffu, mx1, 2));

        float mn0 = fmaxf(m0r, mx0);
        float mn1 = fmaxf(m1r, mx1);
        float cr0 = ex2f(m0r - mn0);
        float cr1 = ex2f(m1r - mn1);
        m0r = mn0; m1r = mn1;

        float rs0 = 0.0f, rs1 = 0.0f;
        #pragma unroll
        for (int j = 0; j < 8; ++j) {
            float p0 = ex2f(sacc[j][0] - mn0);
            float p1 = ex2f(sacc[j][1] - mn0);
            float p2 = ex2f(sacc[j][2] - mn1);
            float p3 = ex2f(sacc[j][3] - mn1);
            rs0 += p0 + p1; rs1 += p2 + p3;
            sacc[j][0] = tf32r(p0); sacc[j][1] = tf32r(p1);
            sacc[j][2] = tf32r(p2); sacc[j][3] = tf32r(p3);
        }
        rs0 += __shfl_xor_sync(0xffffffffu, rs0, 1);
        rs0 += __shfl_xor_sync(0xffffffffu, rs0, 2);
        rs1 += __shfl_xor_sync(0xffffffffu, rs1, 1);
        rs1 += __shfl_xor_sync(0xffffffffu, rs1, 2);
        l0 = l0 * cr0 + rs0;
        l1 = l1 * cr1 + rs1;

        #pragma unroll
        for (int j = 0; j < 8; ++j) {
            pacc[j][0] *= cr0; pacc[j][1] *= cr0;
            pacc[j][2] *= cr1; pacc[j][3] *= cr1;
        }

        // O += P @ V : permute S accumulator frag -> PV A-frag via quad shuffles
        #pragma unroll
        for (int jj = 0; jj < 8; ++jj) {
            float q0 = __shfl_sync(0xffffffffu, sacc[jj][0], src0);
            float q1 = __shfl_sync(0xffffffffu, sacc[jj][1], src0);
            float q2 = __shfl_sync(0xffffffffu, sacc[jj][2], src0);
            float q3 = __shfl_sync(0xffffffffu, sacc[jj][3], src0);
            float r0 = __shfl_sync(0xffffffffu, sacc[jj][0], src0 + 2);
            float r1 = __shfl_sync(0xffffffffu, sacc[jj][1], src0 + 2);
            float r2 = __shfl_sync(0xffffffffu, sacc[jj][2], src0 + 2);
            float r3 = __shfl_sync(0xffffffffu, sacc[jj][3], src0 + 2);
            float pf[4];
            pf[0] = odd ? q1 : q0;   // P[g][8jj + t]
            pf[1] = odd ? q3 : q2;   // P[g+8][8jj + t]
            pf[2] = odd ? r1 : r0;   // P[g][8jj + t + 4]
            pf[3] = odd ? r3 : r2;   // P[g+8][8jj + t + 4]
            const int ks = jj * 8;
            #pragma unroll
            for (int j = 0; j < 8; ++j) {
                float b0 = Vb[(ks + t) * AT_STR + j * 8 + g];
                float b1 = Vb[(ks + t + 4) * AT_STR + j * 8 + g];
                mma_tf32(pacc[j], pf, b0, b1);
            }
        }

        __syncthreads();   // all warps done reading stage s
        if (n + 2 < nTiles) issueKV(n + 2, s);
    }

    // Epilogue: normalize, rna-round (proj GEMM consumes raw), store
    float linv0 = 1.0f / l0, linv1 = 1.0f / l1;
    float* obase = out + (size_t)(b * T_ + qt * ATM) * D_ + h * DH_;
    #pragma unroll
    for (int j = 0; j < 8; ++j) {
        *(float2*)(obase + (size_t)(m0 + g) * D_ + j * 8 + 2 * t) =
            make_float2(tf32r(pacc[j][0] * linv0), tf32r(pacc[j][1] * linv0));
        *(float2*)(obase + (size_t)(m0 + g + 8) * D_ + j * 8 + 2 * t) =
            make_float2(tf32r(pacc[j][2] * linv1), tf32r(pacc[j][3] * linv1));
    }
}

// ---------------------------------------------------------------------------
extern "C" void kernel_launch(void* const* d_in, const int* in_sizes, int n_in,
                              void* d_out, int out_size)
{
    const float* x      = (const float*)d_in[0];
    const float* w_attn = (const float*)d_in[1];
    const float* w_proj = (const float*)d_in[2];
    float* out = (float*)d_out;

    float *qkv, *att, *xr, *war, *wpr;
    cudaGetSymbolAddress((void**)&qkv, g_qkv);
    cudaGetSymbolAddress((void**)&att, g_att);
    cudaGetSymbolAddress((void**)&xr,  g_xr);
    cudaGetSymbolAddress((void**)&war, g_war);
    cudaGetSymbolAddress((void**)&wpr, g_wpr);

    cudaFuncSetAttribute(gemm_nt_tf32,
                         cudaFuncAttributeMaxDynamicSharedMemorySize, GEMM_SMEM_BYTES);
    cudaFuncSetAttribute(attn_mma_kernel,
                         cudaFuncAttributeMaxDynamicSharedMemorySize, ATTN_SMEM_BYTES);

    // 0) Pre-round inputs to tf32 (rna) so GEMMs can cp.async raw
    {
        int n4x = NTOK * D_ / 4, n4a = E3 * D_ / 4, n4p = D_ * D_ / 4;
        round_tf32_kernel<<<(n4x + 255) / 256, 256>>>((const float4*)x, (float4*)xr, n4x);
        round_tf32_kernel<<<(n4a + 255) / 256, 256>>>((const float4*)w_attn, (float4*)war, n4a);
        round_tf32_kernel<<<(n4p + 255) / 256, 256>>>((const float4*)w_proj, (float4*)wpr, n4p);
    }

    // 1) QKV projection (epilogue rounds; Q columns pre-scaled by 0.125*log2e)
    {
        dim3 grid(E3 / BN, NTOK / BM);
        gemm_nt_tf32<<<grid, 256, GEMM_SMEM_BYTES>>>(xr, war, qkv, NTOK, E3, D_, 1);
    }

    // 2) Causal flash attention (tensor cores, double-buffered cp.async)
    {
        dim3 grid(T_ / ATM, H_, B_);
        attn_mma_kernel<<<grid, 256, ATTN_SMEM_BYTES>>>(qkv, att);
    }

    // 3) Output projection (plain f32 epilogue — final output)
    {
        dim3 grid(D_ / BN, NTOK / BM);
        gemm_nt_tf32<<<grid, 256, GEMM_SMEM_BYTES>>>(att, wpr, out, NTOK, D_, D_, 0);
    }
}

// round 16
// speedup vs baseline: 2.0226x; 2.0226x over previous
#include <cuda_runtime.h>
#include <cuda_fp16.h>
#include <math.h>
#include <stdint.h>

// Problem constants
#define B_   4
#define T_   2048
#define D_   1024
#define H_   16
#define DH_  64
#define NTOK (B_ * T_)     // 8192
#define E3   (3 * D_)      // 3072

// softmax scale folded with log2(e): logits come out in base-2 units
#define QSCALE 0.18033688011112042f   // 0.125 * log2(e)

// Scratch (device globals: allocation-free rule)
__device__ __align__(16) __half g_qkv[NTOK * E3];   // half qkv (Q pre-scaled)
__device__ __align__(16) __half g_att[NTOK * D_];   // half attention output
__device__ __align__(16) __half g_xh [NTOK * D_];   // half-rounded x
__device__ __align__(16) __half g_wah[E3 * D_];     // half-rounded w_attn
__device__ __align__(16) __half g_wph[D_ * D_];     // half-rounded w_proj

// ---------------------------------------------------------------------------
// Helpers
// ---------------------------------------------------------------------------
__device__ __forceinline__ float ex2f(float x) {
    float r;
    asm("ex2.approx.ftz.f32 %0, %1;" : "=f"(r) : "f"(x));
    return r;
}

__device__ __forceinline__ uint32_t packh2(float lo, float hi) {
    __half2 h = __floats2half2_rn(lo, hi);
    return *reinterpret_cast<uint32_t*>(&h);
}

__device__ __forceinline__ void mma_f16(float* c, const uint32_t* a,
                                        uint32_t b0, uint32_t b1) {
    asm volatile(
        "mma.sync.aligned.m16n8k16.row.col.f32.f16.f16.f32 "
        "{%0,%1,%2,%3}, {%4,%5,%6,%7}, {%8,%9}, {%0,%1,%2,%3};\n"
        : "+f"(c[0]), "+f"(c[1]), "+f"(c[2]), "+f"(c[3])
        : "r"(a[0]), "r"(a[1]), "r"(a[2]), "r"(a[3]), "r"(b0), "r"(b1));
}

__device__ __forceinline__ void ldsm_x4(uint32_t* r, const void* p) {
    uint32_t a = (uint32_t)__cvta_generic_to_shared(p);
    asm volatile("ldmatrix.sync.aligned.m8n8.x4.shared.b16 {%0,%1,%2,%3}, [%4];"
                 : "=r"(r[0]), "=r"(r[1]), "=r"(r[2]), "=r"(r[3]) : "r"(a));
}

__device__ __forceinline__ void ldsm_x4_t(uint32_t* r, const void* p) {
    uint32_t a = (uint32_t)__cvta_generic_to_shared(p);
    asm volatile("ldmatrix.sync.aligned.m8n8.x4.trans.shared.b16 {%0,%1,%2,%3}, [%4];"
                 : "=r"(r[0]), "=r"(r[1]), "=r"(r[2]), "=r"(r[3]) : "r"(a));
}

__device__ __forceinline__ void cp_async16(void* smem_dst, const void* gsrc) {
    uint32_t s = (uint32_t)__cvta_generic_to_shared(smem_dst);
    asm volatile("cp.async.cg.shared.global [%0], [%1], 16;\n" :: "r"(s), "l"(gsrc) : "memory");
}
__device__ __forceinline__ void cp_commit() {
    asm volatile("cp.async.commit_group;\n" ::: "memory");
}
template<int N>
__device__ __forceinline__ void cp_wait() {
    asm volatile("cp.async.wait_group %0;\n" :: "n"(N) : "memory");
}

// ---------------------------------------------------------------------------
// Round f32 -> f16 (rn), elementwise. 4 floats -> 4 halfs per thread.
// ---------------------------------------------------------------------------
__global__ void round_half_kernel(const float4* __restrict__ in,
                                  uint2* __restrict__ out, int n4)
{
    int i = blockIdx.x * blockDim.x + threadIdx.x;
    if (i < n4) {
        float4 v = in[i];
        uint2 o;
        o.x = packh2(v.x, v.y);
        o.y = packh2(v.z, v.w);
        out[i] = o;
    }
}

// ---------------------------------------------------------------------------
// FP16 NT GEMM (f32 accum). BM=BN=128, BK=64 halfs, 2-stage cp.async double
// buffer, LDSM fragment loads, mma.m16n8k16. 256 threads, warp tile 64x32.
// qkv_mode=1: C = half, Q cols scaled by QSCALE. mode=0: C = float (output).
// ---------------------------------------------------------------------------
#define BM 128
#define BN 128
#define BKH 64
#define TSTRH 72                                  // halfs (64 + 8 pad)
#define STAGE_HALFS (BM * TSTRH)                  // 9216 halfs per matrix
#define GEMM_SMEM_BYTES (2 * 2 * STAGE_HALFS * 2) // 73728

__global__ void __launch_bounds__(256, 2)
gemm_nt_f16(const __half* __restrict__ A, const __half* __restrict__ Bm,
            void* __restrict__ Cv, int M, int N, int K, int qkv_mode)
{
    extern __shared__ __half smg[];

    const int tid  = threadIdx.x;
    const int lane = tid & 31;
    const int warp = tid >> 5;
    const int wm   = (warp >> 2) * 64;
    const int wn   = (warp & 3) * 32;
    const int m0   = blockIdx.y * BM;
    const int n0   = blockIdx.x * BN;

    // LDSM per-thread source pattern (8-half = 16B granules)
    const int l8 = lane & 7;
    const int aR = ((lane >> 3) & 1) * 8;
    const int aC = (lane >> 4) * 8;
    const int bR = ((lane >> 4) & 1) * 8;
    const int bC = ((lane >> 3) & 1) * 8;

    float acc[4][4][4] = {};

    const int nIter = K / BKH;   // 16

    auto issue = [&](int it, int s) {
        __half* As = smg + s * 2 * STAGE_HALFS;
        __half* Bs = As + STAGE_HALFS;
        const int k0 = it * BKH;
        #pragma unroll
        for (int i = 0; i < 4; ++i) {
            int c  = tid + i * 256;          // 1024 16B-chunks per matrix
            int r  = c >> 3;                 // 8 chunks per row
            int ck = (c & 7) * 8;            // half offset
            cp_async16(&As[r * TSTRH + ck], &A[(size_t)(m0 + r) * K + k0 + ck]);
            cp_async16(&Bs[r * TSTRH + ck], &Bm[(size_t)(n0 + r) * K + k0 + ck]);
        }
        cp_commit();
    };

    issue(0, 0);
    issue(1, 1);

    for (int it = 0; it < nIter; ++it) {
        const int s = it & 1;
        cp_wait<1>();
        __syncthreads();

        const __half* As = smg + s * 2 * STAGE_HALFS;
        const __half* Bs = As + STAGE_HALFS;

        #pragma unroll
        for (int ks = 0; ks < BKH; ks += 16) {
            uint32_t af[4][4], bf[2][4];
            #pragma unroll
            for (int mi = 0; mi < 4; ++mi)
                ldsm_x4(af[mi], &As[(wm + mi * 16 + aR + l8) * TSTRH + ks + aC]);
            #pragma unroll
            for (int p = 0; p < 2; ++p)
                ldsm_x4(bf[p], &Bs[(wn + p * 16 + bR + l8) * TSTRH + ks + bC]);
            #pragma unroll
            for (int mi = 0; mi < 4; ++mi)
                #pragma unroll
                for (int nj = 0; nj < 4; ++nj)
                    mma_f16(acc[mi][nj], af[mi],
                            bf[nj >> 1][(nj & 1) * 2], bf[nj >> 1][(nj & 1) * 2 + 1]);
        }
        __syncthreads();
        if (it + 2 < nIter) issue(it + 2, s);
        else cp_commit();   // keep group accounting uniform
    }

    const int g = lane >> 2, t = lane & 3;
    if (qkv_mode) {
        __half* Ch = (__half*)Cv;
        const float esc = (n0 < D_) ? QSCALE : 1.0f;
        #pragma unroll
        for (int mi = 0; mi < 4; ++mi) {
            int row = m0 + wm + mi * 16 + g;
            #pragma unroll
            for (int nj = 0; nj < 4; ++nj) {
                int col = n0 + wn + nj * 8 + 2 * t;
                *(uint32_t*)&Ch[(size_t)row * N + col] =
                    packh2(acc[mi][nj][0] * esc, acc[mi][nj][1] * esc);
                *(uint32_t*)&Ch[(size_t)(row + 8) * N + col] =
                    packh2(acc[mi][nj][2] * esc, acc[mi][nj][3] * esc);
            }
        }
    } else {
        float* Cf = (float*)Cv;
        #pragma unroll
        for (int mi = 0; mi < 4; ++mi) {
            int row = m0 + wm + mi * 16 + g;
            #pragma unroll
            for (int nj = 0; nj < 4; ++nj) {
                int col = n0 + wn + nj * 8 + 2 * t;
                *(float2*)&Cf[(size_t)row * N + col] =
                    make_float2(acc[mi][nj][0], acc[mi][nj][1]);
                *(float2*)&Cf[(size_t)(row + 8) * N + col] =
                    make_float2(acc[mi][nj][2], acc[mi][nj][3]);
            }
        }
    }
}

// ---------------------------------------------------------------------------
// FP16 flash attention (f32 softmax + accum). BLOCK_M=128 (8 warps x 16 q
// rows), key tiles of 64, DH=64, 256 threads. K/V double-buffered cp.async;
// Q/K frags via LDSM, V B-frags via LDSM.trans; S-frag -> P-frag is a local
// half2 pack (fp16 fragment layouts line up exactly — no shuffles).
// ---------------------------------------------------------------------------
#define ATM 128
#define ATSTR 72
// Qb[128][72] + 2 stages x (Kb[64][72] + Vb[64][72]) halfs
#define ATTN_SMEM_BYTES ((ATM + 4 * 64) * ATSTR * 2)   // 55296

__global__ void __launch_bounds__(256, 2)
attn_f16_kernel(const __half* __restrict__ qkv, __half* __restrict__ att)
{
    extern __shared__ __half sma[];
    __half* Qb = sma;                    // [row][d]
    __half* KV = Qb + ATM * ATSTR;       // stage s: K at s*2*64*ATSTR, V at +64*ATSTR

    const int tid  = threadIdx.x;
    const int lane = tid & 31;
    const int warp = tid >> 5;
    const int g    = lane >> 2;
    const int t    = lane & 3;
    const int m0   = warp * 16;
    const int qt   = gridDim.x - 1 - blockIdx.x;   // big tiles first
    const int h    = blockIdx.y;
    const int b    = blockIdx.z;

    const int l8 = lane & 7;
    const int aR = ((lane >> 3) & 1) * 8;
    const int aC = (lane >> 4) * 8;
    const int bR = ((lane >> 4) & 1) * 8;
    const int bC = ((lane >> 3) & 1) * 8;
    const int vR = ((lane >> 3) & 1) * 8;          // trans: matrices 1,3 -> +8 keys
    const int vC = ((lane >> 4) & 1) * 8;          // trans: matrices 2,3 -> +8 d

    // Q tile load (half, pre-scaled by GEMM epilogue)
    const __half* qbase = qkv + (size_t)(b * T_ + qt * ATM) * E3 + h * DH_;
    #pragma unroll
    for (int i = 0; i < 4; ++i) {
        int c = tid + i * 256;           // 1024 chunks (128 rows x 8)
        int r = c >> 3, ck = (c & 7) * 8;
        cp_async16(&Qb[r * ATSTR + ck], qbase + (size_t)r * E3 + ck);
    }
    cp_commit();

    const int nTiles = 2 * qt + 2;

    auto issueKV = [&](int n, int s) {
        const __half* kbase = qkv + (size_t)(b * T_ + n * 64) * E3 + D_ + h * DH_;
        __half* Kb = KV + s * 2 * 64 * ATSTR;
        __half* Vb = Kb + 64 * ATSTR;
        #pragma unroll
        for (int i = 0; i < 2; ++i) {
            int c = tid + i * 256;       // 512 chunks each (64 rows x 8)
            int r = c >> 3, ck = (c & 7) * 8;
            const __half* kp = kbase + (size_t)r * E3 + ck;
            cp_async16(&Kb[r * ATSTR + ck], kp);
            cp_async16(&Vb[r * ATSTR + ck], kp + D_);
        }
        cp_commit();
    };

    issueKV(0, 0);
    issueKV(1, 1);

    float pacc[8][4] = {};
    float m0r = -3.0e38f, m1r = -3.0e38f;
    float l0 = 0.0f, l1 = 0.0f;

    for (int n = 0; n < nTiles; ++n) {
        const int s = n & 1;
        if (n + 1 < nTiles) cp_wait<1>();
        else                cp_wait<0>();
        __syncthreads();

        const __half* Kb = KV + s * 2 * 64 * ATSTR;
        const __half* Vb = Kb + 64 * ATSTR;

        // S = Q @ K^T  (m16n8k16; 4 k-steps over DH=64)
        float sacc[8][4] = {};
        #pragma unroll
        for (int ks = 0; ks < 64; ks += 16) {
            uint32_t aq[4], kb[4][4];
            ldsm_x4(aq, &Qb[(m0 + aR + l8) * ATSTR + ks + aC]);
            #pragma unroll
            for (int p = 0; p < 4; ++p)
                ldsm_x4(kb[p], &Kb[(p * 16 + bR + l8) * ATSTR + ks + bC]);
            #pragma unroll
            for (int j = 0; j < 8; ++j)
                mma_f16(sacc[j], aq,
                        kb[j >> 1][(j & 1) * 2], kb[j >> 1][(j & 1) * 2 + 1]);
        }

        // Causal mask on tiles crossing the diagonal
        if (n >= 2 * qt) {
            int rg0 = qt * ATM + m0 + g;
            int rg1 = rg0 + 8;
            #pragma unroll
            for (int j = 0; j < 8; ++j) {
                int c0 = n * 64 + j * 8 + 2 * t, c1 = c0 + 1;
                if (c0 > rg0) sacc[j][0] = -3.0e38f;
                if (c1 > rg0) sacc[j][1] = -3.0e38f;
                if (c0 > rg1) sacc[j][2] = -3.0e38f;
                if (c1 > rg1) sacc[j][3] = -3.0e38f;
            }
        }

        // Online softmax in base-2 units
        float mx0 = -3.0e38f, mx1 = -3.0e38f;
        #pragma unroll
        for (int j = 0; j < 8; ++j) {
            mx0 = fmaxf(mx0, fmaxf(sacc[j][0], sacc[j][1]));
            mx1 = fmaxf(mx1, fmaxf(sacc[j][2], sacc[j][3]));
        }
        mx0 = fmaxf(mx0, __shfl_xor_sync(0xffffffffu, mx0, 1));
        mx0 = fmaxf(mx0, __shfl_xor_sync(0xffffffffu, mx0, 2));
        mx1 = fmaxf(mx1, __shfl_xor_sync(0xffffffffu, mx1, 1));
        mx1 = fmaxf(mx1, __shfl_xor_sync(0xffffffffu, mx1, 2));

        float mn0 = fmaxf(m0r, mx0);
        float mn1 = fmaxf(m1r, mx1);
        float cr0 = ex2f(m0r - mn0);
        float cr1 = ex2f(m1r - mn1);
        m0r = mn0; m1r = mn1;

        float rs0 = 0.0f, rs1 = 0.0f;
        #pragma unroll
        for (int j = 0; j < 8; ++j) {
            sacc[j][0] = ex2f(sacc[j][0] - mn0);
            sacc[j][1] = ex2f(sacc[j][1] - mn0);
            sacc[j][2] = ex2f(sacc[j][2] - mn1);
            sacc[j][3] = ex2f(sacc[j][3] - mn1);
            rs0 += sacc[j][0] + sacc[j][1];
            rs1 += sacc[j][2] + sacc[j][3];
        }
        rs0 += __shfl_xor_sync(0xffffffffu, rs0, 1);
        rs0 += __shfl_xor_sync(0xffffffffu, rs0, 2);
        rs1 += __shfl_xor_sync(0xffffffffu, rs1, 1);
        rs1 += __shfl_xor_sync(0xffffffffu, rs1, 2);
        l0 = l0 * cr0 + rs0;
        l1 = l1 * cr1 + rs1;

        #pragma unroll
        for (int j = 0; j < 8; ++j) {
            pacc[j][0] *= cr0; pacc[j][1] *= cr0;
            pacc[j][2] *= cr1; pacc[j][3] *= cr1;
        }

        // O += P @ V : S-frag cols (2t,2t+1) == PV A-frag k-pairs -> local pack
        #pragma unroll
        for (int u = 0; u < 4; ++u) {
            uint32_t pf[4];
            pf[0] = packh2(sacc[2 * u][0],     sacc[2 * u][1]);
            pf[1] = packh2(sacc[2 * u][2],     sacc[2 * u][3]);
            pf[2] = packh2(sacc[2 * u + 1][0], sacc[2 * u + 1][1]);
            pf[3] = packh2(sacc[2 * u + 1][2], sacc[2 * u + 1][3]);
            uint32_t vb[4][4];
            #pragma unroll
            for (int jp = 0; jp < 4; ++jp)
                ldsm_x4_t(vb[jp], &Vb[(16 * u + vR + l8) * ATSTR + jp * 16 + vC]);
            #pragma unroll
            for (int j = 0; j < 8; ++j)
                mma_f16(pacc[j], pf,
                        vb[j >> 1][(j & 1) * 2], vb[j >> 1][(j & 1) * 2 + 1]);
        }

        __syncthreads();   // all warps done reading stage s
        if (n + 2 < nTiles) issueKV(n + 2, s);
    }

    // Epilogue: normalize, convert to half, store
    float linv0 = 1.0f / l0, linv1 = 1.0f / l1;
    __half* obase = att + (size_t)(b * T_ + qt * ATM) * D_ + h * DH_;
    #pragma unroll
    for (int j = 0; j < 8; ++j) {
        *(uint32_t*)(obase + (size_t)(m0 + g) * D_ + j * 8 + 2 * t) =
            packh2(pacc[j][0] * linv0, pacc[j][1] * linv0);
        *(uint32_t*)(obase + (size_t)(m0 + g + 8) * D_ + j * 8 + 2 * t) =
            packh2(pacc[j][2] * linv1, pacc[j][3] * linv1);
    }
}

// ---------------------------------------------------------------------------
extern "C" void kernel_launch(void* const* d_in, const int* in_sizes, int n_in,
                              void* d_out, int out_size)
{
    const float* x      = (const float*)d_in[0];
    const float* w_attn = (const float*)d_in[1];
    const float* w_proj = (const float*)d_in[2];
    float* out = (float*)d_out;

    __half *qkv, *att, *xh, *wah, *wph;
    cudaGetSymbolAddress((void**)&qkv, g_qkv);
    cudaGetSymbolAddress((void**)&att, g_att);
    cudaGetSymbolAddress((void**)&xh,  g_xh);
    cudaGetSymbolAddress((void**)&wah, g_wah);
    cudaGetSymbolAddress((void**)&wph, g_wph);

    cudaFuncSetAttribute(gemm_nt_f16,
                         cudaFuncAttributeMaxDynamicSharedMemorySize, GEMM_SMEM_BYTES);
    cudaFuncSetAttribute(attn_f16_kernel,
                         cudaFuncAttributeMaxDynamicSharedMemorySize, ATTN_SMEM_BYTES);

    // 0) Round inputs to fp16 (rn)
    {
        int n4x = NTOK * D_ / 4, n4a = E3 * D_ / 4, n4p = D_ * D_ / 4;
        round_half_kernel<<<(n4x + 255) / 256, 256>>>((const float4*)x, (uint2*)xh, n4x);
        round_half_kernel<<<(n4a + 255) / 256, 256>>>((const float4*)w_attn, (uint2*)wah, n4a);
        round_half_kernel<<<(n4p + 255) / 256, 256>>>((const float4*)w_proj, (uint2*)wph, n4p);
    }

    // 1) QKV projection (fp16 mma; epilogue -> half, Q pre-scaled)
    {
        dim3 grid(E3 / BN, NTOK / BM);
        gemm_nt_f16<<<grid, 256, GEMM_SMEM_BYTES>>>(xh, wah, qkv, NTOK, E3, D_, 1);
    }

    // 2) Causal flash attention (fp16 tensor cores)
    {
        dim3 grid(T_ / ATM, H_, B_);
        attn_f16_kernel<<<grid, 256, ATTN_SMEM_BYTES>>>(qkv, att);
    }

    // 3) Output projection (fp16 mma, f32 epilogue — final output)
    {
        dim3 grid(D_ / BN, NTOK / BM);
        gemm_nt_f16<<<grid, 256, GEMM_SMEM_BYTES>>>(att, wph, out, NTOK, D_, D_, 0);
    }
}